// round 11
// baseline (speedup 1.0000x reference)
#include <cuda_runtime.h>
#include <cuda_fp16.h>
#include <math.h>

typedef unsigned int u32;

#define BB 2
#define TT 2048
#define DD 1024
#define HH 16
#define DK 64

#define SEG  4194304          // B*T*D
#define WSEG 1048576          // D*D
// scratch layout (fp16 elements) in g_sh/g_sl:
//  0:qin  SEG:kin  2S:vin  3S:wq  3S+W:wk  3S+2W:wv  3S+3W:wo
//  4S:Q[B,H,T,DK]  5S:K  6S:V  7S:attn[B,T,D]
__device__ __align__(16) __half g_sh[8 * SEG];
__device__ __align__(16) __half g_sl[8 * SEG];

// ---------------------------------------------------------------------------
__device__ __forceinline__ void split2(float x0, float x1, u32 &h, u32 &l)
{
    __half2 hh = __floats2half2_rn(x0, x1);
    float r0 = x0 - __half2float(__low2half(hh));
    float r1 = x1 - __half2float(__high2half(hh));
    __half2 ll = __floats2half2_rn(r0, r1);
    h = *reinterpret_cast<u32*>(&hh);
    l = *reinterpret_cast<u32*>(&ll);
}

__device__ __forceinline__ void mma16816(float* c,
    u32 a0, u32 a1, u32 a2, u32 a3, u32 b0, u32 b1)
{
    asm volatile(
        "mma.sync.aligned.m16n8k16.row.col.f32.f16.f16.f32 "
        "{%0,%1,%2,%3},{%4,%5,%6,%7},{%8,%9},{%0,%1,%2,%3};"
        : "+f"(c[0]), "+f"(c[1]), "+f"(c[2]), "+f"(c[3])
        : "r"(a0), "r"(a1), "r"(a2), "r"(a3), "r"(b0), "r"(b1));
}

__device__ __forceinline__ void ldsm4(u32* r, u32 addr)
{
    asm volatile("ldmatrix.sync.aligned.m8n8.x4.shared.b16 {%0,%1,%2,%3}, [%4];"
        : "=r"(r[0]), "=r"(r[1]), "=r"(r[2]), "=r"(r[3]) : "r"(addr));
}
__device__ __forceinline__ void ldsm4t(u32* r, u32 addr)
{
    asm volatile("ldmatrix.sync.aligned.m8n8.x4.trans.shared.b16 {%0,%1,%2,%3}, [%4];"
        : "=r"(r[0]), "=r"(r[1]), "=r"(r[2]), "=r"(r[3]) : "r"(addr));
}

__device__ __forceinline__ void cpa(u32 dst, const void* src)
{
    asm volatile("cp.async.cg.shared.global [%0], [%1], 16;" :: "r"(dst), "l"(src));
}
__device__ __forceinline__ void cpc() { asm volatile("cp.async.commit_group;"); }
#define CPW(n) asm volatile("cp.async.wait_group %0;" :: "n"(n))

__device__ __forceinline__ float ex2(float x)
{
    float y;
    asm("ex2.approx.ftz.f32 %0, %1;" : "=f"(y) : "f"(x));
    return y;
}

// ---------------------------------------------------------------------------
__global__ void split_inputs(const float* q, const float* k, const float* v,
                             const float* wq, const float* wk, const float* wv,
                             const float* wo)
{
    const float* srcs[7] = {q, k, v, wq, wk, wv, wo};
    const int offs[7] = {0, SEG, 2*SEG, 3*SEG, 3*SEG+WSEG, 3*SEG+2*WSEG, 3*SEG+3*WSEG};
    const int cnts[7] = {SEG, SEG, SEG, WSEG, WSEG, WSEG, WSEG};
    const int sid = blockIdx.y;
    const float* src = srcs[sid];
    const int off = offs[sid], cnt = cnts[sid];
    for (int idx = (blockIdx.x * 256 + threadIdx.x) * 4; idx < cnt;
         idx += gridDim.x * 1024) {
        float4 x = *(const float4*)(src + idx);
        u32 h0, l0, h1, l1;
        split2(x.x, x.y, h0, l0);
        split2(x.z, x.w, h1, l1);
        *(u32*)(g_sh + off + idx)     = h0;
        *(u32*)(g_sh + off + idx + 2) = h1;
        *(u32*)(g_sl + off + idx)     = l0;
        *(u32*)(g_sl + off + idx + 2) = l1;
    }
}

// ---------------------------------------------------------------------------
// Projection GEMM, 2-term fp16 EFT: C = (Ah + Al) @ Wh^T.
// cp.async 3-stage (depth-2 prefetch), 512 threads (16 warps 4x4),
// warp tile 32x32, CTA tile 128x128, k-tile 32.
// smem stage: Ah(10240B) Al Bh; stride 30720 B; 3 stages = 92160 B.
// ---------------------------------------------------------------------------
#define PJS 20

extern __shared__ u32 smdyn[];

__global__ void __launch_bounds__(512) proj_mma(float* __restrict__ fout, int qkv)
{
    const int z = qkv ? blockIdx.z : 3;
    const int aoff = (z == 3) ? 7 * SEG : z * SEG;
    const int woff = 3 * SEG + z * WSEG;
    const __half* Agh = g_sh + aoff;
    const __half* Agl = g_sl + aoff;
    const __half* Bgh = g_sh + woff;

    const int t = threadIdx.x, lane = t & 31, wid = t >> 5;
    const int g = lane >> 2, ctg = lane & 3;
    const int wm = wid >> 2, wn = wid & 3;          // 4 x 4 warps
    const int m0 = blockIdx.y * 128, n0 = blockIdx.x * 128;

    const u32 sb = (u32)__cvta_generic_to_shared(smdyn);
    const u32 lro = ((lane & 7) + ((lane >> 3) & 1) * 8) * 80 + (lane >> 4) * 16;

    const int r_ = t >> 2, sg_ = t & 3;
    const u32 d_ = (u32)(r_ * PJS + sg_ * 4) * 4;

    float c[2][4][4];
    #pragma unroll
    for (int i = 0; i < 2; i++)
        #pragma unroll
        for (int j = 0; j < 4; j++)
            #pragma unroll
            for (int r = 0; r < 4; r++) c[i][j][r] = 0.f;

    auto issue = [&](int k0, int st) {
        const u32 stb = sb + (u32)st * 30720;
        cpa(stb         + d_, Agh + (size_t)(m0 + r_) * 1024 + k0 + sg_ * 8);
        cpa(stb + 10240 + d_, Agl + (size_t)(m0 + r_) * 1024 + k0 + sg_ * 8);
        cpa(stb + 20480 + d_, Bgh + (size_t)(n0 + r_) * 1024 + k0 + sg_ * 8);
        cpc();
    };

    issue(0, 0);
    issue(32, 1);

    for (int kt = 0; kt < 32; kt++) {
        if (kt < 31) { CPW(1); } else { CPW(0); }
        __syncthreads();
        if (kt + 2 < 32) issue((kt + 2) * 32, (kt + 2) % 3);

        const u32 stb = sb + (u32)(kt % 3) * 30720;
        const u32 bAh = stb, bAl = stb + 10240, bBh = stb + 20480;

        #pragma unroll
        for (int ch = 0; ch < 2; ch++) {
            u32 a[2][2][4];
            #pragma unroll
            for (int i = 0; i < 2; i++) {
                const u32 ad = (u32)(wm * 32 + i * 16) * 80 + ch * 32 + lro;
                ldsm4(a[i][0], bAh + ad);
                ldsm4(a[i][1], bAl + ad);
            }
            u32 bh_[2][4];
            #pragma unroll
            for (int jp = 0; jp < 2; jp++)
                ldsm4(bh_[jp], bBh + (u32)(wn * 32 + jp * 16) * 80 + ch * 32 + lro);
            #pragma unroll
            for (int jp = 0; jp < 2; jp++)
                #pragma unroll
                for (int jj = 0; jj < 2; jj++) {
                    const int j = jp * 2 + jj;
                    const u32 b0h = bh_[jp][jj], b1h = bh_[jp][2 + jj];
                    #pragma unroll
                    for (int i = 0; i < 2; i++) {
                        mma16816(c[i][j], a[i][0][0], a[i][0][1], a[i][0][2], a[i][0][3], b0h, b1h);
                        mma16816(c[i][j], a[i][1][0], a[i][1][1], a[i][1][2], a[i][1][3], b0h, b1h);
                    }
                }
        }
    }

    // epilogue
    const float scale = (z == 0) ? 0.125f * 1.4426950408889634f : 1.0f;
    if (z < 3) {
        __half* Oh = g_sh + (4 + z) * SEG;
        __half* Ol = g_sl + (4 + z) * SEG;
        #pragma unroll
        for (int i = 0; i < 2; i++)
            #pragma unroll
            for (int h2 = 0; h2 < 2; h2++) {
                const int m = m0 + wm * 32 + i * 16 + h2 * 8 + g;
                const int b = m >> 11, tq = m & 2047;
                #pragma unroll
                for (int j = 0; j < 4; j++) {
                    const int n = n0 + wn * 32 + j * 8 + ctg * 2;
                    const int h = n >> 6, dk = n & 63;
                    u32 hi, lo;
                    split2(c[i][j][h2*2] * scale, c[i][j][h2*2+1] * scale, hi, lo);
                    const size_t e = (((size_t)(b * HH + h) * TT + tq) << 6) + dk;
                    *(u32*)(Oh + e) = hi;
                    if (z == 0) *(u32*)(Ol + e) = lo;   // K/V lo never consumed
                }
            }
    } else {
        #pragma unroll
        for (int i = 0; i < 2; i++)
            #pragma unroll
            for (int h2 = 0; h2 < 2; h2++) {
                const int m = m0 + wm * 32 + i * 16 + h2 * 8 + g;
                #pragma unroll
                for (int j = 0; j < 4; j++) {
                    const int n = n0 + wn * 32 + j * 8 + ctg * 2;
                    *(float2*)(fout + (size_t)m * 1024 + n)
                        = make_float2(c[i][j][h2*2], c[i][j][h2*2+1]);
                }
            }
    }
}

// ---------------------------------------------------------------------------
// Fused attention, 512 threads (16 warps), fp16.
// Pass A: 1-term S (Qh x Kh), 3-stage K pipeline (depth-2).
// Pass B: 2-term S + weights + 1-term AV; fused K+V commit groups, 3 stages.
// smem (bytes): Qh 0  Ql 18432 | K st 36864+st*18432 (3)
//   V st 92160+st*18432 (3) | Wh 147456 (34816) ; total 182272 B.
// ---------------------------------------------------------------------------
__global__ void __launch_bounds__(512) attn_mma(float* __restrict__ wout)
{
    __shared__ float stats[512];

    const int t = threadIdx.x, lane = t & 31, wid = t >> 5;
    const int g = lane >> 2, ctg = lane & 3;
    const int wm = wid >> 2, wn = wid & 3;          // 4 x 4 warps
    const int bh = blockIdx.y;
    const int q0 = blockIdx.x * 128;
    const int head = bh & 15, bb = bh >> 4;

    const __half* Qgh = g_sh + 4 * SEG + (size_t)bh * TT * DK;
    const __half* Qgl = g_sl + 4 * SEG + (size_t)bh * TT * DK;
    const __half* Kgh = g_sh + 5 * SEG + (size_t)bh * TT * DK;
    const __half* Vgh = g_sh + 6 * SEG + (size_t)bh * TT * DK;

    const u32 sb = (u32)__cvta_generic_to_shared(smdyn);
    u32* sWh = smdyn + 36864;                       // u32 index: 147456 B / 4
    const u32 bQh = sb, bQl = sb + 18432;
    const u32 bWh = sb + 147456;

    const u32 lro36 = ((lane & 7) + ((lane >> 3) & 1) * 8) * 144 + (lane >> 4) * 16;
    const u32 lro68 = ((lane & 7) + ((lane >> 3) & 1) * 8) * 272 + (lane >> 4) * 16;

    // copy mapping: 128x64 fp16 tile = 1024 uint4, 2 per thread
    int cr[2], cs[2]; u32 cd[2];
    #pragma unroll
    for (int u = 0; u < 2; u++) {
        const int idx = t + u * 512;
        cr[u] = idx >> 3; cs[u] = idx & 7;
        cd[u] = (u32)(cr[u] * 36 + cs[u] * 4) * 4;
    }

    // ---- load Q tile (hi+lo) ----
    #pragma unroll
    for (int u = 0; u < 2; u++) {
        *(uint4*)(smdyn + cr[u] * 36 + cs[u] * 4) =
            *(const uint4*)(Qgh + (size_t)(q0 + cr[u]) * DK + cs[u] * 8);
        *(uint4*)(smdyn + 4608 + cr[u] * 36 + cs[u] * 4) =
            *(const uint4*)(Qgl + (size_t)(q0 + cr[u]) * DK + cs[u] * 8);
    }

    float l_[4] = {0.f, 0.f, 0.f, 0.f};

    auto issueK = [&](int kt, int st) {
        const u32 stb = sb + 36864u + (u32)st * 18432u;
        #pragma unroll
        for (int u = 0; u < 2; u++)
            cpa(stb + cd[u], Kgh + (size_t)(kt * 128 + cr[u]) * DK + cs[u] * 8);
        cpc();
    };

    issueK(0, 0);
    issueK(1, 1);

    // ============================ pass A ============================
    for (int kt = 0; kt < 16; kt++) {
        if (kt < 15) { CPW(1); } else { CPW(0); }
        __syncthreads();
        if (kt + 2 < 16) issueK(kt + 2, (kt + 2) % 3);

        const u32 bKh = sb + 36864u + (u32)(kt % 3) * 18432u;

        float s[2][4][4];
        #pragma unroll
        for (int i = 0; i < 2; i++)
            #pragma unroll
            for (int j = 0; j < 4; j++)
                #pragma unroll
                for (int r = 0; r < 4; r++) s[i][j][r] = 0.f;

        #pragma unroll
        for (int ch = 0; ch < 4; ch++) {
            u32 a[2][4];
            #pragma unroll
            for (int i = 0; i < 2; i++)
                ldsm4(a[i], bQh + (u32)(wm * 32 + i * 16) * 144 + ch * 32 + lro36);
            #pragma unroll
            for (int jp = 0; jp < 2; jp++) {
                u32 bfh[4];
                ldsm4(bfh, bKh + (u32)(wn * 32 + jp * 16) * 144 + ch * 32 + lro36);
                #pragma unroll
                for (int jj = 0; jj < 2; jj++) {
                    const int j = jp * 2 + jj;
                    #pragma unroll
                    for (int i = 0; i < 2; i++)
                        mma16816(s[i][j], a[i][0], a[i][1], a[i][2], a[i][3],
                                 bfh[jj], bfh[2 + jj]);
                }
            }
        }

        #pragma unroll
        for (int i = 0; i < 2; i++)
            #pragma unroll
            for (int h2 = 0; h2 < 2; h2++) {
                float sum = 0.f;
                #pragma unroll
                for (int j = 0; j < 4; j++)
                    sum += ex2(s[i][j][h2*2]) + ex2(s[i][j][h2*2+1]);
                sum += __shfl_xor_sync(0xffffffffu, sum, 1);
                sum += __shfl_xor_sync(0xffffffffu, sum, 2);
                l_[i * 2 + h2] += sum;
            }
    }

    // ---- merge wn quarters ----
    __syncthreads();
    if (ctg == 0) {
        #pragma unroll
        for (int i = 0; i < 2; i++)
            #pragma unroll
            for (int h2 = 0; h2 < 2; h2++) {
                const int row = wm * 32 + i * 16 + h2 * 8 + g;
                stats[row * 4 + wn] = l_[i * 2 + h2];
            }
    }
    __syncthreads();
    float inv[4];
    #pragma unroll
    for (int i = 0; i < 2; i++)
        #pragma unroll
        for (int h2 = 0; h2 < 2; h2++) {
            const int row = wm * 32 + i * 16 + h2 * 8 + g;
            inv[i * 2 + h2] = 1.f / (stats[row * 4 + 0] + stats[row * 4 + 1]
                                   + stats[row * 4 + 2] + stats[row * 4 + 3]);
        }

    float o[2][2][4];
    #pragma unroll
    for (int i = 0; i < 2; i++)
        #pragma unroll
        for (int j = 0; j < 2; j++)
            #pragma unroll
            for (int r = 0; r < 4; r++) o[i][j][r] = 0.f;

    // fused K+V group per k-tile, 3 stages each
    auto issueKV = [&](int kt, int st) {
        const u32 kb = sb + 36864u + (u32)st * 18432u;
        const u32 vb = sb + 92160u + (u32)st * 18432u;
        #pragma unroll
        for (int u = 0; u < 2; u++) {
            cpa(kb + cd[u], Kgh + (size_t)(kt * 128 + cr[u]) * DK + cs[u] * 8);
            cpa(vb + cd[u], Vgh + (size_t)(kt * 128 + cr[u]) * DK + cs[u] * 8);
        }
        cpc();
    };

    issueKV(0, 0);
    issueKV(1, 1);

    // ============================ pass B ============================
    for (int kt = 0; kt < 16; kt++) {
        if (kt < 15) { CPW(1); } else { CPW(0); }
        __syncthreads();
        if (kt + 2 < 16) issueKV(kt + 2, (kt + 2) % 3);

        const u32 bKh = sb + 36864u + (u32)(kt % 3) * 18432u;
        const u32 bVh = sb + 92160u + (u32)(kt % 3) * 18432u;

        float s[2][4][4];
        #pragma unroll
        for (int i = 0; i < 2; i++)
            #pragma unroll
            for (int j = 0; j < 4; j++)
                #pragma unroll
                for (int r = 0; r < 4; r++) s[i][j][r] = 0.f;

        #pragma unroll
        for (int ch = 0; ch < 4; ch++) {
            u32 a[2][2][4];
            #pragma unroll
            for (int i = 0; i < 2; i++) {
                const u32 ad = (u32)(wm * 32 + i * 16) * 144 + ch * 32 + lro36;
                ldsm4(a[i][0], bQh + ad);
                ldsm4(a[i][1], bQl + ad);
            }
            #pragma unroll
            for (int jp = 0; jp < 2; jp++) {
                u32 bfh[4];
                ldsm4(bfh, bKh + (u32)(wn * 32 + jp * 16) * 144 + ch * 32 + lro36);
                #pragma unroll
                for (int jj = 0; jj < 2; jj++) {
                    const int j = jp * 2 + jj;
                    const u32 b0h = bfh[jj], b1h = bfh[2 + jj];
                    #pragma unroll
                    for (int i = 0; i < 2; i++) {
                        mma16816(s[i][j], a[i][0][0], a[i][0][1], a[i][0][2], a[i][0][3], b0h, b1h);
                        mma16816(s[i][j], a[i][1][0], a[i][1][1], a[i][1][2], a[i][1][3], b0h, b1h);
                    }
                }
            }
        }

        // normalized weights -> gmem + single-fp16 W into smem
        #pragma unroll
        for (int i = 0; i < 2; i++)
            #pragma unroll
            for (int h2 = 0; h2 < 2; h2++) {
                const int idx = i * 2 + h2;
                const int row = wm * 32 + i * 16 + h2 * 8 + g;
                #pragma unroll
                for (int j = 0; j < 4; j++) {
                    const float w0 = ex2(s[i][j][h2*2])   * inv[idx];
                    const float w1 = ex2(s[i][j][h2*2+1]) * inv[idx];
                    if (wout)
                        *(float2*)(wout + ((size_t)bh * TT + q0 + row) * TT
                                        + kt * 128 + wn * 32 + j * 8 + ctg * 2)
                            = make_float2(w0, w1);
                    __half2 wh2 = __floats2half2_rn(w0, w1);
                    sWh[row * 68 + wn * 16 + j * 4 + ctg] = *(u32*)&wh2;
                }
            }

        __syncthreads();   // W visible to all warps before AV

        // AV: O += W @ V   (single term: W x Vh)
        #pragma unroll
        for (int ch = 0; ch < 8; ch++) {
            u32 aw[2][4];
            #pragma unroll
            for (int i = 0; i < 2; i++)
                ldsm4(aw[i], bWh + (u32)(wm * 32 + i * 16) * 272 + ch * 32 + lro68);
            u32 bvh[4];
            const u32 vd = (u32)(ch * 16) * 144 + (u32)(wn * 16) * 2 + lro36;
            ldsm4t(bvh, bVh + vd);
            #pragma unroll
            for (int j = 0; j < 2; j++) {
                #pragma unroll
                for (int i = 0; i < 2; i++)
                    mma16816(o[i][j], aw[i][0], aw[i][1], aw[i][2], aw[i][3],
                             bvh[j * 2], bvh[j * 2 + 1]);
            }
        }
    }

    // epilogue: split O -> attn scratch [B,T,D]
    __half* Oh = g_sh + 7 * SEG;
    __half* Ol = g_sl + 7 * SEG;
    #pragma unroll
    for (int i = 0; i < 2; i++)
        #pragma unroll
        for (int h2 = 0; h2 < 2; h2++) {
            const int row = q0 + wm * 32 + i * 16 + h2 * 8 + g;
            #pragma unroll
            for (int j = 0; j < 2; j++) {
                const int col = head * 64 + wn * 16 + j * 8 + ctg * 2;
                u32 hi, lo;
                split2(o[i][j][h2*2], o[i][j][h2*2+1], hi, lo);
                const size_t e = ((size_t)bb * TT + row) * DD + col;
                *(u32*)(Oh + e) = hi;
                *(u32*)(Ol + e) = lo;
            }
        }
}

// ---------------------------------------------------------------------------
extern "C" void kernel_launch(void* const* d_in, const int* in_sizes, int n_in,
                              void* d_out, int out_size)
{
    const float* query = (const float*)d_in[0];
    const float* key_  = (const float*)d_in[1];
    const float* value = (const float*)d_in[2];
    const float* W_q   = (const float*)d_in[3];
    const float* W_k   = (const float*)d_in[4];
    const float* W_v   = (const float*)d_in[5];
    const float* W_o   = (const float*)d_in[6];

    split_inputs<<<dim3(1024, 7), 256>>>(query, key_, value, W_q, W_k, W_v, W_o);

    const int psmem = 92160;
    cudaFuncSetAttribute(proj_mma,
                         cudaFuncAttributeMaxDynamicSharedMemorySize, psmem);
    proj_mma<<<dim3(8, 32, 3), 512, psmem>>>(nullptr, 1);   // Q, K, V

    const size_t OUT_E = (size_t)BB * TT * DD;
    const size_t W_E   = (size_t)BB * HH * TT * (size_t)TT;
    float* wout = nullptr;
    if ((size_t)out_size >= OUT_E + W_E)
        wout = (float*)d_out + OUT_E;

    const int asmem = 182272;
    cudaFuncSetAttribute(attn_mma,
                         cudaFuncAttributeMaxDynamicSharedMemorySize, asmem);
    attn_mma<<<dim3(TT / 128, BB * HH), 512, asmem>>>(wout);

    proj_mma<<<dim3(8, 32, 1), 512, psmem>>>((float*)d_out, 0);   // O projection
}

// round 14
// speedup vs baseline: 1.0824x; 1.0824x over previous
#include <cuda_runtime.h>
#include <cuda_fp16.h>
#include <math.h>

typedef unsigned int u32;

#define BB 2
#define TT 2048
#define DD 1024
#define HH 16
#define DK 64

#define SEG  4194304          // B*T*D
#define WSEG 1048576          // D*D
// scratch layout (fp16 elements) in g_sh/g_sl:
//  0:qin  SEG:kin  2S:vin  3S:wq  3S+W:wk  3S+2W:wv  3S+3W:wo
//  4S:Q[B,H,T,DK]  5S:K  6S:V  7S:attn[B,T,D]
__device__ __align__(16) __half g_sh[8 * SEG];
__device__ __align__(16) __half g_sl[8 * SEG];

// ---------------------------------------------------------------------------
__device__ __forceinline__ void split2(float x0, float x1, u32 &h, u32 &l)
{
    __half2 hh = __floats2half2_rn(x0, x1);
    float r0 = x0 - __half2float(__low2half(hh));
    float r1 = x1 - __half2float(__high2half(hh));
    __half2 ll = __floats2half2_rn(r0, r1);
    h = *reinterpret_cast<u32*>(&hh);
    l = *reinterpret_cast<u32*>(&ll);
}

__device__ __forceinline__ void mma16816(float* c,
    u32 a0, u32 a1, u32 a2, u32 a3, u32 b0, u32 b1)
{
    asm volatile(
        "mma.sync.aligned.m16n8k16.row.col.f32.f16.f16.f32 "
        "{%0,%1,%2,%3},{%4,%5,%6,%7},{%8,%9},{%0,%1,%2,%3};"
        : "+f"(c[0]), "+f"(c[1]), "+f"(c[2]), "+f"(c[3])
        : "r"(a0), "r"(a1), "r"(a2), "r"(a3), "r"(b0), "r"(b1));
}

__device__ __forceinline__ void ldsm4(u32* r, u32 addr)
{
    asm volatile("ldmatrix.sync.aligned.m8n8.x4.shared.b16 {%0,%1,%2,%3}, [%4];"
        : "=r"(r[0]), "=r"(r[1]), "=r"(r[2]), "=r"(r[3]) : "r"(addr));
}
__device__ __forceinline__ void ldsm4t(u32* r, u32 addr)
{
    asm volatile("ldmatrix.sync.aligned.m8n8.x4.trans.shared.b16 {%0,%1,%2,%3}, [%4];"
        : "=r"(r[0]), "=r"(r[1]), "=r"(r[2]), "=r"(r[3]) : "r"(addr));
}

__device__ __forceinline__ void cpa(u32 dst, const void* src)
{
    asm volatile("cp.async.cg.shared.global [%0], [%1], 16;" :: "r"(dst), "l"(src));
}
__device__ __forceinline__ void cpc() { asm volatile("cp.async.commit_group;"); }
#define CPW(n) asm volatile("cp.async.wait_group %0;" :: "n"(n))

__device__ __forceinline__ float ex2(float x)
{
    float y;
    asm("ex2.approx.ftz.f32 %0, %1;" : "=f"(y) : "f"(x));
    return y;
}

// ---------------------------------------------------------------------------
__global__ void split_inputs(const float* q, const float* k, const float* v,
                             const float* wq, const float* wk, const float* wv,
                             const float* wo)
{
    const float* srcs[7] = {q, k, v, wq, wk, wv, wo};
    const int offs[7] = {0, SEG, 2*SEG, 3*SEG, 3*SEG+WSEG, 3*SEG+2*WSEG, 3*SEG+3*WSEG};
    const int cnts[7] = {SEG, SEG, SEG, WSEG, WSEG, WSEG, WSEG};
    const int sid = blockIdx.y;
    const float* src = srcs[sid];
    const int off = offs[sid], cnt = cnts[sid];
    const bool wantlo = (sid < 3);      // weight lo halves are never read
    for (int idx = (blockIdx.x * 256 + threadIdx.x) * 4; idx < cnt;
         idx += gridDim.x * 1024) {
        float4 x = *(const float4*)(src + idx);
        u32 h0, l0, h1, l1;
        split2(x.x, x.y, h0, l0);
        split2(x.z, x.w, h1, l1);
        *(u32*)(g_sh + off + idx)     = h0;
        *(u32*)(g_sh + off + idx + 2) = h1;
        if (wantlo) {
            *(u32*)(g_sl + off + idx)     = l0;
            *(u32*)(g_sl + off + idx + 2) = l1;
        }
    }
}

// ---------------------------------------------------------------------------
// Projection GEMM, 2-term fp16 EFT: C = (Ah + Al) @ Wh^T.
// cp.async 2-stage, 512 threads (16 warps 4x4), warp tile 32x64.
// CTA tile 128x256, k-tile 32.
// smem stage: Ah(10240B) Al(10240) Bh(20480); stride 40960 B; 2 stages.
// ---------------------------------------------------------------------------
#define PJS 20

extern __shared__ u32 smdyn[];

__global__ void __launch_bounds__(512) proj_mma(float* __restrict__ fout, int qkv)
{
    const int z = qkv ? blockIdx.z : 3;
    const int aoff = (z == 3) ? 7 * SEG : z * SEG;
    const int woff = 3 * SEG + z * WSEG;
    const __half* Agh = g_sh + aoff;
    const __half* Agl = g_sl + aoff;
    const __half* Bgh = g_sh + woff;

    const int t = threadIdx.x, lane = t & 31, wid = t >> 5;
    const int g = lane >> 2, ctg = lane & 3;
    const int wm = wid >> 2, wn = wid & 3;          // 4 x 4 warps
    const int m0 = blockIdx.y * 128, n0 = blockIdx.x * 256;

    const u32 sb = (u32)__cvta_generic_to_shared(smdyn);
    const u32 lro = ((lane & 7) + ((lane >> 3) & 1) * 8) * 80 + (lane >> 4) * 16;

    // copy mapping: A 512 uint4 (1/thread each for hi,lo); B 1024 uint4 (2/thread)
    const int ra_ = t >> 2, sa_ = t & 3;
    const u32 da_ = (u32)(ra_ * PJS + sa_ * 4) * 4;
    int rb_[2], sgb_[2]; u32 db_[2];
    #pragma unroll
    for (int u = 0; u < 2; u++) {
        const int idx = t + u * 512;
        rb_[u] = idx >> 2; sgb_[u] = idx & 3;
        db_[u] = (u32)(rb_[u] * PJS + sgb_[u] * 4) * 4;
    }

    float c[2][8][4];
    #pragma unroll
    for (int i = 0; i < 2; i++)
        #pragma unroll
        for (int j = 0; j < 8; j++)
            #pragma unroll
            for (int r = 0; r < 4; r++) c[i][j][r] = 0.f;

    auto issue = [&](int k0, int st) {
        const u32 stb = sb + (u32)st * 40960;
        cpa(stb         + da_, Agh + (size_t)(m0 + ra_) * 1024 + k0 + sa_ * 8);
        cpa(stb + 10240 + da_, Agl + (size_t)(m0 + ra_) * 1024 + k0 + sa_ * 8);
        #pragma unroll
        for (int u = 0; u < 2; u++)
            cpa(stb + 20480 + db_[u],
                Bgh + (size_t)(n0 + rb_[u]) * 1024 + k0 + sgb_[u] * 8);
        cpc();
    };

    issue(0, 0);

    for (int kt = 0; kt < 32; kt++) {
        CPW(0);
        __syncthreads();
        if (kt < 31) issue((kt + 1) * 32, (kt + 1) & 1);

        const u32 stb = sb + (u32)(kt & 1) * 40960;
        const u32 bAh = stb, bAl = stb + 10240, bBh = stb + 20480;

        #pragma unroll
        for (int ch = 0; ch < 2; ch++) {
            u32 a[2][2][4];
            #pragma unroll
            for (int i = 0; i < 2; i++) {
                const u32 ad = (u32)(wm * 32 + i * 16) * 80 + ch * 32 + lro;
                ldsm4(a[i][0], bAh + ad);
                ldsm4(a[i][1], bAl + ad);
            }
            u32 bh_[4][4];
            #pragma unroll
            for (int jp = 0; jp < 4; jp++)
                ldsm4(bh_[jp], bBh + (u32)(wn * 64 + jp * 16) * 80 + ch * 32 + lro);
            #pragma unroll
            for (int jp = 0; jp < 4; jp++)
                #pragma unroll
                for (int jj = 0; jj < 2; jj++) {
                    const int j = jp * 2 + jj;
                    const u32 b0h = bh_[jp][jj], b1h = bh_[jp][2 + jj];
                    #pragma unroll
                    for (int i = 0; i < 2; i++) {
                        mma16816(c[i][j], a[i][0][0], a[i][0][1], a[i][0][2], a[i][0][3], b0h, b1h);
                        mma16816(c[i][j], a[i][1][0], a[i][1][1], a[i][1][2], a[i][1][3], b0h, b1h);
                    }
                }
        }
    }

    // epilogue
    const float scale = (z == 0) ? 0.125f * 1.4426950408889634f : 1.0f;
    if (z < 3) {
        __half* Oh = g_sh + (4 + z) * SEG;
        __half* Ol = g_sl + (4 + z) * SEG;
        #pragma unroll
        for (int i = 0; i < 2; i++)
            #pragma unroll
            for (int h2 = 0; h2 < 2; h2++) {
                const int m = m0 + wm * 32 + i * 16 + h2 * 8 + g;
                const int b = m >> 11, tq = m & 2047;
                #pragma unroll
                for (int j = 0; j < 8; j++) {
                    const int n = n0 + wn * 64 + j * 8 + ctg * 2;
                    const int h = n >> 6, dk = n & 63;
                    u32 hi, lo;
                    split2(c[i][j][h2*2] * scale, c[i][j][h2*2+1] * scale, hi, lo);
                    const size_t e = (((size_t)(b * HH + h) * TT + tq) << 6) + dk;
                    *(u32*)(Oh + e) = hi;
                    if (z == 0) *(u32*)(Ol + e) = lo;   // K/V lo never consumed
                }
            }
    } else {
        #pragma unroll
        for (int i = 0; i < 2; i++)
            #pragma unroll
            for (int h2 = 0; h2 < 2; h2++) {
                const int m = m0 + wm * 32 + i * 16 + h2 * 8 + g;
                #pragma unroll
                for (int j = 0; j < 8; j++) {
                    const int n = n0 + wn * 64 + j * 8 + ctg * 2;
                    *(float2*)(fout + (size_t)m * 1024 + n)
                        = make_float2(c[i][j][h2*2], c[i][j][h2*2+1]);
                }
            }
    }
}

// ---------------------------------------------------------------------------
// Fused attention, 512 threads (16 warps), fp16.  (Identical to R10 champion.)
// Pass A: 1-term S (Qh x Kh).  Pass B: 2-term S ((Qh+Ql) x Kh) + weights +
// 1-term AV (W fp16 x Vh).  K-lo never touched.
// smem (bytes): Qh 0  Ql 18432 | K st0 36864  st1 55296 (hi only)
//   Vh 73728 | Wh 92160 (34816) ; total 126976 B.
// ---------------------------------------------------------------------------
__global__ void __launch_bounds__(512) attn_mma(float* __restrict__ wout)
{
    __shared__ float stats[512];

    const int t = threadIdx.x, lane = t & 31, wid = t >> 5;
    const int g = lane >> 2, ctg = lane & 3;
    const int wm = wid >> 2, wn = wid & 3;          // 4 x 4 warps
    const int bh = blockIdx.y;
    const int q0 = blockIdx.x * 128;
    const int head = bh & 15, bb = bh >> 4;

    const __half* Qgh = g_sh + 4 * SEG + (size_t)bh * TT * DK;
    const __half* Qgl = g_sl + 4 * SEG + (size_t)bh * TT * DK;
    const __half* Kgh = g_sh + 5 * SEG + (size_t)bh * TT * DK;
    const __half* Vgh = g_sh + 6 * SEG + (size_t)bh * TT * DK;

    const u32 sb = (u32)__cvta_generic_to_shared(smdyn);
    u32* sWh = smdyn + 23040;                       // u32 index of Wh region
    const u32 bQh = sb, bQl = sb + 18432;
    const u32 bVh = sb + 73728;
    const u32 bWh = sb + 92160;

    const u32 lro36 = ((lane & 7) + ((lane >> 3) & 1) * 8) * 144 + (lane >> 4) * 16;
    const u32 lro68 = ((lane & 7) + ((lane >> 3) & 1) * 8) * 272 + (lane >> 4) * 16;

    // copy mapping: 128x64 fp16 tile = 1024 uint4, 2 per thread
    int cr[2], cs[2]; u32 cd[2];
    #pragma unroll
    for (int u = 0; u < 2; u++) {
        const int idx = t + u * 512;
        cr[u] = idx >> 3; cs[u] = idx & 7;
        cd[u] = (u32)(cr[u] * 36 + cs[u] * 4) * 4;
    }

    // ---- load Q tile (hi+lo) ----
    #pragma unroll
    for (int u = 0; u < 2; u++) {
        *(uint4*)(smdyn + cr[u] * 36 + cs[u] * 4) =
            *(const uint4*)(Qgh + (size_t)(q0 + cr[u]) * DK + cs[u] * 8);
        *(uint4*)(smdyn + 4608 + cr[u] * 36 + cs[u] * 4) =
            *(const uint4*)(Qgl + (size_t)(q0 + cr[u]) * DK + cs[u] * 8);
    }

    float l_[4] = {0.f, 0.f, 0.f, 0.f};

    auto issueK = [&](int kt, int st) {
        const u32 stb = sb + 36864u + (u32)st * 18432u;
        #pragma unroll
        for (int u = 0; u < 2; u++)
            cpa(stb + cd[u], Kgh + (size_t)(kt * 128 + cr[u]) * DK + cs[u] * 8);
        cpc();
    };

    issueK(0, 0);

    // ============================ pass A ============================
    for (int kt = 0; kt < 16; kt++) {
        CPW(0);
        __syncthreads();
        if (kt < 15) issueK(kt + 1, (kt + 1) & 1);

        const u32 bKh = sb + 36864u + (u32)(kt & 1) * 18432u;

        float s[2][4][4];
        #pragma unroll
        for (int i = 0; i < 2; i++)
            #pragma unroll
            for (int j = 0; j < 4; j++)
                #pragma unroll
                for (int r = 0; r < 4; r++) s[i][j][r] = 0.f;

        #pragma unroll
        for (int ch = 0; ch < 4; ch++) {
            u32 a[2][4];
            #pragma unroll
            for (int i = 0; i < 2; i++)
                ldsm4(a[i], bQh + (u32)(wm * 32 + i * 16) * 144 + ch * 32 + lro36);
            #pragma unroll
            for (int jp = 0; jp < 2; jp++) {
                u32 bfh[4];
                ldsm4(bfh, bKh + (u32)(wn * 32 + jp * 16) * 144 + ch * 32 + lro36);
                #pragma unroll
                for (int jj = 0; jj < 2; jj++) {
                    const int j = jp * 2 + jj;
                    #pragma unroll
                    for (int i = 0; i < 2; i++)
                        mma16816(s[i][j], a[i][0], a[i][1], a[i][2], a[i][3],
                                 bfh[jj], bfh[2 + jj]);
                }
            }
        }

        #pragma unroll
        for (int i = 0; i < 2; i++)
            #pragma unroll
            for (int h2 = 0; h2 < 2; h2++) {
                float sum = 0.f;
                #pragma unroll
                for (int j = 0; j < 4; j++)
                    sum += ex2(s[i][j][h2*2]) + ex2(s[i][j][h2*2+1]);
                sum += __shfl_xor_sync(0xffffffffu, sum, 1);
                sum += __shfl_xor_sync(0xffffffffu, sum, 2);
                l_[i * 2 + h2] += sum;
            }
    }

    // ---- merge wn quarters ----
    __syncthreads();
    if (ctg == 0) {
        #pragma unroll
        for (int i = 0; i < 2; i++)
            #pragma unroll
            for (int h2 = 0; h2 < 2; h2++) {
                const int row = wm * 32 + i * 16 + h2 * 8 + g;
                stats[row * 4 + wn] = l_[i * 2 + h2];
            }
    }
    __syncthreads();
    float inv[4];
    #pragma unroll
    for (int i = 0; i < 2; i++)
        #pragma unroll
        for (int h2 = 0; h2 < 2; h2++) {
            const int row = wm * 32 + i * 16 + h2 * 8 + g;
            inv[i * 2 + h2] = 1.f / (stats[row * 4 + 0] + stats[row * 4 + 1]
                                   + stats[row * 4 + 2] + stats[row * 4 + 3]);
        }

    float o[2][2][4];
    #pragma unroll
    for (int i = 0; i < 2; i++)
        #pragma unroll
        for (int j = 0; j < 2; j++)
            #pragma unroll
            for (int r = 0; r < 4; r++) o[i][j][r] = 0.f;

    auto issueV = [&](int kt) {
        #pragma unroll
        for (int u = 0; u < 2; u++)
            cpa(bVh + cd[u], Vgh + (size_t)(kt * 128 + cr[u]) * DK + cs[u] * 8);
        cpc();
    };

    issueK(0, 0);

    // ============================ pass B ============================
    for (int kt = 0; kt < 16; kt++) {
        CPW(0);
        __syncthreads();
        issueV(kt);
        if (kt < 15) issueK(kt + 1, (kt + 1) & 1);

        const u32 bKh = sb + 36864u + (u32)(kt & 1) * 18432u;

        float s[2][4][4];
        #pragma unroll
        for (int i = 0; i < 2; i++)
            #pragma unroll
            for (int j = 0; j < 4; j++)
                #pragma unroll
                for (int r = 0; r < 4; r++) s[i][j][r] = 0.f;

        #pragma unroll
        for (int ch = 0; ch < 4; ch++) {
            u32 a[2][2][4];
            #pragma unroll
            for (int i = 0; i < 2; i++) {
                const u32 ad = (u32)(wm * 32 + i * 16) * 144 + ch * 32 + lro36;
                ldsm4(a[i][0], bQh + ad);
                ldsm4(a[i][1], bQl + ad);
            }
            #pragma unroll
            for (int jp = 0; jp < 2; jp++) {
                u32 bfh[4];
                ldsm4(bfh, bKh + (u32)(wn * 32 + jp * 16) * 144 + ch * 32 + lro36);
                #pragma unroll
                for (int jj = 0; jj < 2; jj++) {
                    const int j = jp * 2 + jj;
                    const u32 b0h = bfh[jj], b1h = bfh[2 + jj];
                    #pragma unroll
                    for (int i = 0; i < 2; i++) {
                        mma16816(s[i][j], a[i][0][0], a[i][0][1], a[i][0][2], a[i][0][3], b0h, b1h);
                        mma16816(s[i][j], a[i][1][0], a[i][1][1], a[i][1][2], a[i][1][3], b0h, b1h);
                    }
                }
            }
        }

        // normalized weights -> gmem + single-fp16 W into smem
        #pragma unroll
        for (int i = 0; i < 2; i++)
            #pragma unroll
            for (int h2 = 0; h2 < 2; h2++) {
                const int idx = i * 2 + h2;
                const int row = wm * 32 + i * 16 + h2 * 8 + g;
                #pragma unroll
                for (int j = 0; j < 4; j++) {
                    const float w0 = ex2(s[i][j][h2*2])   * inv[idx];
                    const float w1 = ex2(s[i][j][h2*2+1]) * inv[idx];
                    if (wout)
                        *(float2*)(wout + ((size_t)bh * TT + q0 + row) * TT
                                        + kt * 128 + wn * 32 + j * 8 + ctg * 2)
                            = make_float2(w0, w1);
                    __half2 wh2 = __floats2half2_rn(w0, w1);
                    sWh[row * 68 + wn * 16 + j * 4 + ctg] = *(u32*)&wh2;
                }
            }

        if (kt < 15) { CPW(1); } else { CPW(0); }
        __syncthreads();

        // AV: O += W @ V   (single term: W x Vh)
        #pragma unroll
        for (int ch = 0; ch < 8; ch++) {
            u32 aw[2][4];
            #pragma unroll
            for (int i = 0; i < 2; i++)
                ldsm4(aw[i], bWh + (u32)(wm * 32 + i * 16) * 272 + ch * 32 + lro68);
            u32 bvh[4];
            const u32 vd = (u32)(ch * 16) * 144 + (u32)(wn * 16) * 2 + lro36;
            ldsm4t(bvh, bVh + vd);
            #pragma unroll
            for (int j = 0; j < 2; j++) {
                #pragma unroll
                for (int i = 0; i < 2; i++)
                    mma16816(o[i][j], aw[i][0], aw[i][1], aw[i][2], aw[i][3],
                             bvh[j * 2], bvh[j * 2 + 1]);
            }
        }
    }

    // epilogue: split O -> attn scratch [B,T,D]
    __half* Oh = g_sh + 7 * SEG;
    __half* Ol = g_sl + 7 * SEG;
    #pragma unroll
    for (int i = 0; i < 2; i++)
        #pragma unroll
        for (int h2 = 0; h2 < 2; h2++) {
            const int row = q0 + wm * 32 + i * 16 + h2 * 8 + g;
            #pragma unroll
            for (int j = 0; j < 2; j++) {
                const int col = head * 64 + wn * 16 + j * 8 + ctg * 2;
                u32 hi, lo;
                split2(o[i][j][h2*2], o[i][j][h2*2+1], hi, lo);
                const size_t e = ((size_t)bb * TT + row) * DD + col;
                *(u32*)(Oh + e) = hi;
                *(u32*)(Ol + e) = lo;
            }
        }
}

// ---------------------------------------------------------------------------
extern "C" void kernel_launch(void* const* d_in, const int* in_sizes, int n_in,
                              void* d_out, int out_size)
{
    const float* query = (const float*)d_in[0];
    const float* key_  = (const float*)d_in[1];
    const float* value = (const float*)d_in[2];
    const float* W_q   = (const float*)d_in[3];
    const float* W_k   = (const float*)d_in[4];
    const float* W_v   = (const float*)d_in[5];
    const float* W_o   = (const float*)d_in[6];

    split_inputs<<<dim3(1024, 7), 256>>>(query, key_, value, W_q, W_k, W_v, W_o);

    const int psmem = 81920;
    cudaFuncSetAttribute(proj_mma,
                         cudaFuncAttributeMaxDynamicSharedMemorySize, psmem);
    proj_mma<<<dim3(4, 32, 3), 512, psmem>>>(nullptr, 1);   // Q, K, V

    const size_t OUT_E = (size_t)BB * TT * DD;
    const size_t W_E   = (size_t)BB * HH * TT * (size_t)TT;
    float* wout = nullptr;
    if ((size_t)out_size >= OUT_E + W_E)
        wout = (float*)d_out + OUT_E;

    const int asmem = 126976;
    cudaFuncSetAttribute(attn_mma,
                         cudaFuncAttributeMaxDynamicSharedMemorySize, asmem);
    attn_mma<<<dim3(TT / 128, BB * HH), 512, asmem>>>(wout);

    proj_mma<<<dim3(4, 32, 1), 512, psmem>>>((float*)d_out, 0);   // O projection
}

// round 15
// speedup vs baseline: 1.1186x; 1.0335x over previous
#include <cuda_runtime.h>
#include <cuda_fp16.h>
#include <math.h>

typedef unsigned int u32;

#define BB 2
#define TT 2048
#define DD 1024
#define HH 16
#define DK 64

#define SEG  4194304          // B*T*D
#define WSEG 1048576          // D*D
// scratch layout (fp16 elements) in g_sh/g_sl:
//  0:qin  SEG:kin  2S:vin  3S:wq  3S+W:wk  3S+2W:wv  3S+3W:wo
//  4S:Q[B,H,T,DK]  5S:K  6S:V  7S:attn[B,T,D]
__device__ __align__(16) __half g_sh[8 * SEG];
__device__ __align__(16) __half g_sl[8 * SEG];

// ---------------------------------------------------------------------------
__device__ __forceinline__ void split2(float x0, float x1, u32 &h, u32 &l)
{
    __half2 hh = __floats2half2_rn(x0, x1);
    float r0 = x0 - __half2float(__low2half(hh));
    float r1 = x1 - __half2float(__high2half(hh));
    __half2 ll = __floats2half2_rn(r0, r1);
    h = *reinterpret_cast<u32*>(&hh);
    l = *reinterpret_cast<u32*>(&ll);
}

__device__ __forceinline__ void mma16816(float* c,
    u32 a0, u32 a1, u32 a2, u32 a3, u32 b0, u32 b1)
{
    asm volatile(
        "mma.sync.aligned.m16n8k16.row.col.f32.f16.f16.f32 "
        "{%0,%1,%2,%3},{%4,%5,%6,%7},{%8,%9},{%0,%1,%2,%3};"
        : "+f"(c[0]), "+f"(c[1]), "+f"(c[2]), "+f"(c[3])
        : "r"(a0), "r"(a1), "r"(a2), "r"(a3), "r"(b0), "r"(b1));
}

__device__ __forceinline__ void ldsm4(u32* r, u32 addr)
{
    asm volatile("ldmatrix.sync.aligned.m8n8.x4.shared.b16 {%0,%1,%2,%3}, [%4];"
        : "=r"(r[0]), "=r"(r[1]), "=r"(r[2]), "=r"(r[3]) : "r"(addr));
}
__device__ __forceinline__ void ldsm4t(u32* r, u32 addr)
{
    asm volatile("ldmatrix.sync.aligned.m8n8.x4.trans.shared.b16 {%0,%1,%2,%3}, [%4];"
        : "=r"(r[0]), "=r"(r[1]), "=r"(r[2]), "=r"(r[3]) : "r"(addr));
}

__device__ __forceinline__ void cpa(u32 dst, const void* src)
{
    asm volatile("cp.async.cg.shared.global [%0], [%1], 16;" :: "r"(dst), "l"(src));
}
__device__ __forceinline__ void cpc() { asm volatile("cp.async.commit_group;"); }
#define CPW(n) asm volatile("cp.async.wait_group %0;" :: "n"(n))

__device__ __forceinline__ float ex2(float x)
{
    float y;
    asm("ex2.approx.ftz.f32 %0, %1;" : "=f"(y) : "f"(x));
    return y;
}

// ---------------------------------------------------------------------------
__global__ void split_inputs(const float* q, const float* k, const float* v,
                             const float* wq, const float* wk, const float* wv,
                             const float* wo)
{
    const float* srcs[7] = {q, k, v, wq, wk, wv, wo};
    const int offs[7] = {0, SEG, 2*SEG, 3*SEG, 3*SEG+WSEG, 3*SEG+2*WSEG, 3*SEG+3*WSEG};
    const int cnts[7] = {SEG, SEG, SEG, WSEG, WSEG, WSEG, WSEG};
    const int sid = blockIdx.y;
    const float* src = srcs[sid];
    const int off = offs[sid], cnt = cnts[sid];
    const bool wantlo = (sid < 2);      // only q,k input lo halves are consumed
    for (int idx = (blockIdx.x * 256 + threadIdx.x) * 4; idx < cnt;
         idx += gridDim.x * 1024) {
        float4 x = *(const float4*)(src + idx);
        u32 h0, l0, h1, l1;
        split2(x.x, x.y, h0, l0);
        split2(x.z, x.w, h1, l1);
        *(u32*)(g_sh + off + idx)     = h0;
        *(u32*)(g_sh + off + idx + 2) = h1;
        if (wantlo) {
            *(u32*)(g_sl + off + idx)     = l0;
            *(u32*)(g_sl + off + idx + 2) = l1;
        }
    }
}

// ---------------------------------------------------------------------------
// Projection GEMM, fp16 EFT: C = (Ah [+ Al]) @ Wh^T.
// Q,K (z=0,1): 2-term A.  V (z=2), O (z=3): 1-term (pure fp16 A).
// cp.async 2-stage, 512 threads (16 warps 4x4), warp tile 32x64.
// CTA tile 128x256, k-tile 32.
// smem stage: Ah(10240B) Al(10240) Bh(20480); stride 40960 B; 2 stages.
// ---------------------------------------------------------------------------
#define PJS 20

extern __shared__ u32 smdyn[];

__global__ void __launch_bounds__(512) proj_mma(float* __restrict__ fout, int qkv)
{
    const int z = qkv ? blockIdx.z : 3;
    const bool two = (z <= 1);          // 2-term A only for Q,K projections
    const int aoff = (z == 3) ? 7 * SEG : z * SEG;
    const int woff = 3 * SEG + z * WSEG;
    const __half* Agh = g_sh + aoff;
    const __half* Agl = g_sl + aoff;
    const __half* Bgh = g_sh + woff;

    const int t = threadIdx.x, lane = t & 31, wid = t >> 5;
    const int g = lane >> 2, ctg = lane & 3;
    const int wm = wid >> 2, wn = wid & 3;          // 4 x 4 warps
    const int m0 = blockIdx.y * 128, n0 = blockIdx.x * 256;

    const u32 sb = (u32)__cvta_generic_to_shared(smdyn);
    const u32 lro = ((lane & 7) + ((lane >> 3) & 1) * 8) * 80 + (lane >> 4) * 16;

    // copy mapping: A 512 uint4 (1/thread each for hi,lo); B 1024 uint4 (2/thread)
    const int ra_ = t >> 2, sa_ = t & 3;
    const u32 da_ = (u32)(ra_ * PJS + sa_ * 4) * 4;
    int rb_[2], sgb_[2]; u32 db_[2];
    #pragma unroll
    for (int u = 0; u < 2; u++) {
        const int idx = t + u * 512;
        rb_[u] = idx >> 2; sgb_[u] = idx & 3;
        db_[u] = (u32)(rb_[u] * PJS + sgb_[u] * 4) * 4;
    }

    float c[2][8][4];
    #pragma unroll
    for (int i = 0; i < 2; i++)
        #pragma unroll
        for (int j = 0; j < 8; j++)
            #pragma unroll
            for (int r = 0; r < 4; r++) c[i][j][r] = 0.f;

    auto issue = [&](int k0, int st) {
        const u32 stb = sb + (u32)st * 40960;
        cpa(stb + da_, Agh + (size_t)(m0 + ra_) * 1024 + k0 + sa_ * 8);
        if (two)
            cpa(stb + 10240 + da_, Agl + (size_t)(m0 + ra_) * 1024 + k0 + sa_ * 8);
        #pragma unroll
        for (int u = 0; u < 2; u++)
            cpa(stb + 20480 + db_[u],
                Bgh + (size_t)(n0 + rb_[u]) * 1024 + k0 + sgb_[u] * 8);
        cpc();
    };

    issue(0, 0);

    for (int kt = 0; kt < 32; kt++) {
        CPW(0);
        __syncthreads();
        if (kt < 31) issue((kt + 1) * 32, (kt + 1) & 1);

        const u32 stb = sb + (u32)(kt & 1) * 40960;
        const u32 bAh = stb, bAl = stb + 10240, bBh = stb + 20480;

        #pragma unroll
        for (int ch = 0; ch < 2; ch++) {
            u32 a[2][2][4];
            #pragma unroll
            for (int i = 0; i < 2; i++) {
                const u32 ad = (u32)(wm * 32 + i * 16) * 80 + ch * 32 + lro;
                ldsm4(a[i][0], bAh + ad);
                if (two) ldsm4(a[i][1], bAl + ad);
            }
            u32 bh_[4][4];
            #pragma unroll
            for (int jp = 0; jp < 4; jp++)
                ldsm4(bh_[jp], bBh + (u32)(wn * 64 + jp * 16) * 80 + ch * 32 + lro);
            #pragma unroll
            for (int jp = 0; jp < 4; jp++)
                #pragma unroll
                for (int jj = 0; jj < 2; jj++) {
                    const int j = jp * 2 + jj;
                    const u32 b0h = bh_[jp][jj], b1h = bh_[jp][2 + jj];
                    #pragma unroll
                    for (int i = 0; i < 2; i++) {
                        mma16816(c[i][j], a[i][0][0], a[i][0][1], a[i][0][2], a[i][0][3], b0h, b1h);
                        if (two)
                            mma16816(c[i][j], a[i][1][0], a[i][1][1], a[i][1][2], a[i][1][3], b0h, b1h);
                    }
                }
        }
    }

    // epilogue
    const float scale = (z == 0) ? 0.125f * 1.4426950408889634f : 1.0f;
    if (z < 3) {
        __half* Oh = g_sh + (4 + z) * SEG;
        __half* Ol = g_sl + (4 + z) * SEG;
        #pragma unroll
        for (int i = 0; i < 2; i++)
            #pragma unroll
            for (int h2 = 0; h2 < 2; h2++) {
                const int m = m0 + wm * 32 + i * 16 + h2 * 8 + g;
                const int b = m >> 11, tq = m & 2047;
                #pragma unroll
                for (int j = 0; j < 8; j++) {
                    const int n = n0 + wn * 64 + j * 8 + ctg * 2;
                    const int h = n >> 6, dk = n & 63;
                    u32 hi, lo;
                    split2(c[i][j][h2*2] * scale, c[i][j][h2*2+1] * scale, hi, lo);
                    const size_t e = (((size_t)(b * HH + h) * TT + tq) << 6) + dk;
                    *(u32*)(Oh + e) = hi;
                    if (z == 0) *(u32*)(Ol + e) = lo;   // K/V lo never consumed
                }
            }
    } else {
        #pragma unroll
        for (int i = 0; i < 2; i++)
            #pragma unroll
            for (int h2 = 0; h2 < 2; h2++) {
                const int m = m0 + wm * 32 + i * 16 + h2 * 8 + g;
                #pragma unroll
                for (int j = 0; j < 8; j++) {
                    const int n = n0 + wn * 64 + j * 8 + ctg * 2;
                    *(float2*)(fout + (size_t)m * 1024 + n)
                        = make_float2(c[i][j][h2*2], c[i][j][h2*2+1]);
                }
            }
    }
}

// ---------------------------------------------------------------------------
// Fused attention, 512 threads (16 warps), fp16.  (Identical to R14.)
// Pass A: 1-term S (Qh x Kh).  Pass B: 2-term S ((Qh+Ql) x Kh) + weights +
// 1-term AV (W fp16 x Vh).  K-lo never touched.
// smem (bytes): Qh 0  Ql 18432 | K st0 36864  st1 55296 (hi only)
//   Vh 73728 | Wh 92160 (34816) ; total 126976 B.
// ---------------------------------------------------------------------------
__global__ void __launch_bounds__(512) attn_mma(float* __restrict__ wout)
{
    __shared__ float stats[512];

    const int t = threadIdx.x, lane = t & 31, wid = t >> 5;
    const int g = lane >> 2, ctg = lane & 3;
    const int wm = wid >> 2, wn = wid & 3;          // 4 x 4 warps
    const int bh = blockIdx.y;
    const int q0 = blockIdx.x * 128;
    const int head = bh & 15, bb = bh >> 4;

    const __half* Qgh = g_sh + 4 * SEG + (size_t)bh * TT * DK;
    const __half* Qgl = g_sl + 4 * SEG + (size_t)bh * TT * DK;
    const __half* Kgh = g_sh + 5 * SEG + (size_t)bh * TT * DK;
    const __half* Vgh = g_sh + 6 * SEG + (size_t)bh * TT * DK;

    const u32 sb = (u32)__cvta_generic_to_shared(smdyn);
    u32* sWh = smdyn + 23040;                       // u32 index of Wh region
    const u32 bQh = sb, bQl = sb + 18432;
    const u32 bVh = sb + 73728;
    const u32 bWh = sb + 92160;

    const u32 lro36 = ((lane & 7) + ((lane >> 3) & 1) * 8) * 144 + (lane >> 4) * 16;
    const u32 lro68 = ((lane & 7) + ((lane >> 3) & 1) * 8) * 272 + (lane >> 4) * 16;

    // copy mapping: 128x64 fp16 tile = 1024 uint4, 2 per thread
    int cr[2], cs[2]; u32 cd[2];
    #pragma unroll
    for (int u = 0; u < 2; u++) {
        const int idx = t + u * 512;
        cr[u] = idx >> 3; cs[u] = idx & 7;
        cd[u] = (u32)(cr[u] * 36 + cs[u] * 4) * 4;
    }

    // ---- load Q tile (hi+lo) ----
    #pragma unroll
    for (int u = 0; u < 2; u++) {
        *(uint4*)(smdyn + cr[u] * 36 + cs[u] * 4) =
            *(const uint4*)(Qgh + (size_t)(q0 + cr[u]) * DK + cs[u] * 8);
        *(uint4*)(smdyn + 4608 + cr[u] * 36 + cs[u] * 4) =
            *(const uint4*)(Qgl + (size_t)(q0 + cr[u]) * DK + cs[u] * 8);
    }

    float l_[4] = {0.f, 0.f, 0.f, 0.f};

    auto issueK = [&](int kt, int st) {
        const u32 stb = sb + 36864u + (u32)st * 18432u;
        #pragma unroll
        for (int u = 0; u < 2; u++)
            cpa(stb + cd[u], Kgh + (size_t)(kt * 128 + cr[u]) * DK + cs[u] * 8);
        cpc();
    };

    issueK(0, 0);

    // ============================ pass A ============================
    for (int kt = 0; kt < 16; kt++) {
        CPW(0);
        __syncthreads();
        if (kt < 15) issueK(kt + 1, (kt + 1) & 1);

        const u32 bKh = sb + 36864u + (u32)(kt & 1) * 18432u;

        float s[2][4][4];
        #pragma unroll
        for (int i = 0; i < 2; i++)
            #pragma unroll
            for (int j = 0; j < 4; j++)
                #pragma unroll
                for (int r = 0; r < 4; r++) s[i][j][r] = 0.f;

        #pragma unroll
        for (int ch = 0; ch < 4; ch++) {
            u32 a[2][4];
            #pragma unroll
            for (int i = 0; i < 2; i++)
                ldsm4(a[i], bQh + (u32)(wm * 32 + i * 16) * 144 + ch * 32 + lro36);
            #pragma unroll
            for (int jp = 0; jp < 2; jp++) {
                u32 bfh[4];
                ldsm4(bfh, bKh + (u32)(wn * 32 + jp * 16) * 144 + ch * 32 + lro36);
                #pragma unroll
                for (int jj = 0; jj < 2; jj++) {
                    const int j = jp * 2 + jj;
                    #pragma unroll
                    for (int i = 0; i < 2; i++)
                        mma16816(s[i][j], a[i][0], a[i][1], a[i][2], a[i][3],
                                 bfh[jj], bfh[2 + jj]);
                }
            }
        }

        #pragma unroll
        for (int i = 0; i < 2; i++)
            #pragma unroll
            for (int h2 = 0; h2 < 2; h2++) {
                float sum = 0.f;
                #pragma unroll
                for (int j = 0; j < 4; j++)
                    sum += ex2(s[i][j][h2*2]) + ex2(s[i][j][h2*2+1]);
                sum += __shfl_xor_sync(0xffffffffu, sum, 1);
                sum += __shfl_xor_sync(0xffffffffu, sum, 2);
                l_[i * 2 + h2] += sum;
            }
    }

    // ---- merge wn quarters ----
    __syncthreads();
    if (ctg == 0) {
        #pragma unroll
        for (int i = 0; i < 2; i++)
            #pragma unroll
            for (int h2 = 0; h2 < 2; h2++) {
                const int row = wm * 32 + i * 16 + h2 * 8 + g;
                stats[row * 4 + wn] = l_[i * 2 + h2];
            }
    }
    __syncthreads();
    float inv[4];
    #pragma unroll
    for (int i = 0; i < 2; i++)
        #pragma unroll
        for (int h2 = 0; h2 < 2; h2++) {
            const int row = wm * 32 + i * 16 + h2 * 8 + g;
            inv[i * 2 + h2] = 1.f / (stats[row * 4 + 0] + stats[row * 4 + 1]
                                   + stats[row * 4 + 2] + stats[row * 4 + 3]);
        }

    float o[2][2][4];
    #pragma unroll
    for (int i = 0; i < 2; i++)
        #pragma unroll
        for (int j = 0; j < 2; j++)
            #pragma unroll
            for (int r = 0; r < 4; r++) o[i][j][r] = 0.f;

    auto issueV = [&](int kt) {
        #pragma unroll
        for (int u = 0; u < 2; u++)
            cpa(bVh + cd[u], Vgh + (size_t)(kt * 128 + cr[u]) * DK + cs[u] * 8);
        cpc();
    };

    issueK(0, 0);

    // ============================ pass B ============================
    for (int kt = 0; kt < 16; kt++) {
        CPW(0);
        __syncthreads();
        issueV(kt);
        if (kt < 15) issueK(kt + 1, (kt + 1) & 1);

        const u32 bKh = sb + 36864u + (u32)(kt & 1) * 18432u;

        float s[2][4][4];
        #pragma unroll
        for (int i = 0; i < 2; i++)
            #pragma unroll
            for (int j = 0; j < 4; j++)
                #pragma unroll
                for (int r = 0; r < 4; r++) s[i][j][r] = 0.f;

        #pragma unroll
        for (int ch = 0; ch < 4; ch++) {
            u32 a[2][2][4];
            #pragma unroll
            for (int i = 0; i < 2; i++) {
                const u32 ad = (u32)(wm * 32 + i * 16) * 144 + ch * 32 + lro36;
                ldsm4(a[i][0], bQh + ad);
                ldsm4(a[i][1], bQl + ad);
            }
            #pragma unroll
            for (int jp = 0; jp < 2; jp++) {
                u32 bfh[4];
                ldsm4(bfh, bKh + (u32)(wn * 32 + jp * 16) * 144 + ch * 32 + lro36);
                #pragma unroll
                for (int jj = 0; jj < 2; jj++) {
                    const int j = jp * 2 + jj;
                    const u32 b0h = bfh[jj], b1h = bfh[2 + jj];
                    #pragma unroll
                    for (int i = 0; i < 2; i++) {
                        mma16816(s[i][j], a[i][0][0], a[i][0][1], a[i][0][2], a[i][0][3], b0h, b1h);
                        mma16816(s[i][j], a[i][1][0], a[i][1][1], a[i][1][2], a[i][1][3], b0h, b1h);
                    }
                }
            }
        }

        // normalized weights -> gmem + single-fp16 W into smem
        #pragma unroll
        for (int i = 0; i < 2; i++)
            #pragma unroll
            for (int h2 = 0; h2 < 2; h2++) {
                const int idx = i * 2 + h2;
                const int row = wm * 32 + i * 16 + h2 * 8 + g;
                #pragma unroll
                for (int j = 0; j < 4; j++) {
                    const float w0 = ex2(s[i][j][h2*2])   * inv[idx];
                    const float w1 = ex2(s[i][j][h2*2+1]) * inv[idx];
                    if (wout)
                        *(float2*)(wout + ((size_t)bh * TT + q0 + row) * TT
                                        + kt * 128 + wn * 32 + j * 8 + ctg * 2)
                            = make_float2(w0, w1);
                    __half2 wh2 = __floats2half2_rn(w0, w1);
                    sWh[row * 68 + wn * 16 + j * 4 + ctg] = *(u32*)&wh2;
                }
            }

        if (kt < 15) { CPW(1); } else { CPW(0); }
        __syncthreads();

        // AV: O += W @ V   (single term: W x Vh)
        #pragma unroll
        for (int ch = 0; ch < 8; ch++) {
            u32 aw[2][4];
            #pragma unroll
            for (int i = 0; i < 2; i++)
                ldsm4(aw[i], bWh + (u32)(wm * 32 + i * 16) * 272 + ch * 32 + lro68);
            u32 bvh[4];
            const u32 vd = (u32)(ch * 16) * 144 + (u32)(wn * 16) * 2 + lro36;
            ldsm4t(bvh, bVh + vd);
            #pragma unroll
            for (int j = 0; j < 2; j++) {
                #pragma unroll
                for (int i = 0; i < 2; i++)
                    mma16816(o[i][j], aw[i][0], aw[i][1], aw[i][2], aw[i][3],
                             bvh[j * 2], bvh[j * 2 + 1]);
            }
        }
    }

    // epilogue: split O -> attn scratch [B,T,D]  (hi only consumed downstream)
    __half* Oh = g_sh + 7 * SEG;
    __half* Ol = g_sl + 7 * SEG;
    #pragma unroll
    for (int i = 0; i < 2; i++)
        #pragma unroll
        for (int h2 = 0; h2 < 2; h2++) {
            const int row = q0 + wm * 32 + i * 16 + h2 * 8 + g;
            #pragma unroll
            for (int j = 0; j < 2; j++) {
                const int col = head * 64 + wn * 16 + j * 8 + ctg * 2;
                u32 hi, lo;
                split2(o[i][j][h2*2], o[i][j][h2*2+1], hi, lo);
                const size_t e = ((size_t)bb * TT + row) * DD + col;
                *(u32*)(Oh + e) = hi;
                *(u32*)(Ol + e) = lo;
            }
        }
}

// ---------------------------------------------------------------------------
extern "C" void kernel_launch(void* const* d_in, const int* in_sizes, int n_in,
                              void* d_out, int out_size)
{
    const float* query = (const float*)d_in[0];
    const float* key_  = (const float*)d_in[1];
    const float* value = (const float*)d_in[2];
    const float* W_q   = (const float*)d_in[3];
    const float* W_k   = (const float*)d_in[4];
    const float* W_v   = (const float*)d_in[5];
    const float* W_o   = (const float*)d_in[6];

    split_inputs<<<dim3(1024, 7), 256>>>(query, key_, value, W_q, W_k, W_v, W_o);

    const int psmem = 81920;
    cudaFuncSetAttribute(proj_mma,
                         cudaFuncAttributeMaxDynamicSharedMemorySize, psmem);
    proj_mma<<<dim3(4, 32, 3), 512, psmem>>>(nullptr, 1);   // Q, K, V

    const size_t OUT_E = (size_t)BB * TT * DD;
    const size_t W_E   = (size_t)BB * HH * TT * (size_t)TT;
    float* wout = nullptr;
    if ((size_t)out_size >= OUT_E + W_E)
        wout = (float*)d_out + OUT_E;

    const int asmem = 126976;
    cudaFuncSetAttribute(attn_mma,
                         cudaFuncAttributeMaxDynamicSharedMemorySize, asmem);
    attn_mma<<<dim3(TT / 128, BB * HH), 512, asmem>>>(wout);

    proj_mma<<<dim3(4, 32, 1), 512, psmem>>>((float*)d_out, 0);   // O projection
}

// round 17
// speedup vs baseline: 1.2115x; 1.0830x over previous
#include <cuda_runtime.h>
#include <cuda_fp16.h>
#include <math.h>

typedef unsigned int u32;

#define BB 2
#define TT 2048
#define DD 1024
#define HH 16
#define DK 64

#define SEG  4194304          // B*T*D
#define WSEG 1048576          // D*D
// scratch layout (fp16 elements) in g_sh/g_sl:
//  0:qin  SEG:kin  2S:vin  3S:wq  3S+W:wk  3S+2W:wv  3S+3W:wo
//  4S:Q[B,H,T,DK]  5S:K  6S:V  7S:attn[B,T,D]
__device__ __align__(16) __half g_sh[8 * SEG];
__device__ __align__(16) __half g_sl[8 * SEG];

// ---------------------------------------------------------------------------
__device__ __forceinline__ void split2(float x0, float x1, u32 &h, u32 &l)
{
    __half2 hh = __floats2half2_rn(x0, x1);
    float r0 = x0 - __half2float(__low2half(hh));
    float r1 = x1 - __half2float(__high2half(hh));
    __half2 ll = __floats2half2_rn(r0, r1);
    h = *reinterpret_cast<u32*>(&hh);
    l = *reinterpret_cast<u32*>(&ll);
}

__device__ __forceinline__ void mma16816(float* c,
    u32 a0, u32 a1, u32 a2, u32 a3, u32 b0, u32 b1)
{
    asm volatile(
        "mma.sync.aligned.m16n8k16.row.col.f32.f16.f16.f32 "
        "{%0,%1,%2,%3},{%4,%5,%6,%7},{%8,%9},{%0,%1,%2,%3};"
        : "+f"(c[0]), "+f"(c[1]), "+f"(c[2]), "+f"(c[3])
        : "r"(a0), "r"(a1), "r"(a2), "r"(a3), "r"(b0), "r"(b1));
}

__device__ __forceinline__ void ldsm4(u32* r, u32 addr)
{
    asm volatile("ldmatrix.sync.aligned.m8n8.x4.shared.b16 {%0,%1,%2,%3}, [%4];"
        : "=r"(r[0]), "=r"(r[1]), "=r"(r[2]), "=r"(r[3]) : "r"(addr));
}
__device__ __forceinline__ void ldsm4t(u32* r, u32 addr)
{
    asm volatile("ldmatrix.sync.aligned.m8n8.x4.trans.shared.b16 {%0,%1,%2,%3}, [%4];"
        : "=r"(r[0]), "=r"(r[1]), "=r"(r[2]), "=r"(r[3]) : "r"(addr));
}

__device__ __forceinline__ void cpa(u32 dst, const void* src)
{
    asm volatile("cp.async.cg.shared.global [%0], [%1], 16;" :: "r"(dst), "l"(src));
}
__device__ __forceinline__ void cpc() { asm volatile("cp.async.commit_group;"); }
#define CPW(n) asm volatile("cp.async.wait_group %0;" :: "n"(n))

__device__ __forceinline__ float ex2(float x)
{
    float y;
    asm("ex2.approx.ftz.f32 %0, %1;" : "=f"(y) : "f"(x));
    return y;
}

// ---------------------------------------------------------------------------
__global__ void split_inputs(const float* q, const float* k, const float* v,
                             const float* wq, const float* wk, const float* wv,
                             const float* wo)
{
    const float* srcs[7] = {q, k, v, wq, wk, wv, wo};
    const int offs[7] = {0, SEG, 2*SEG, 3*SEG, 3*SEG+WSEG, 3*SEG+2*WSEG, 3*SEG+3*WSEG};
    const int cnts[7] = {SEG, SEG, SEG, WSEG, WSEG, WSEG, WSEG};
    const int sid = blockIdx.y;
    const float* src = srcs[sid];
    const int off = offs[sid], cnt = cnts[sid];
    const bool wantlo = (sid < 2);      // only q,k input lo halves are consumed
    for (int idx = (blockIdx.x * 256 + threadIdx.x) * 4; idx < cnt;
         idx += gridDim.x * 1024) {
        float4 x = *(const float4*)(src + idx);
        u32 h0, l0, h1, l1;
        split2(x.x, x.y, h0, l0);
        split2(x.z, x.w, h1, l1);
        *(u32*)(g_sh + off + idx)     = h0;
        *(u32*)(g_sh + off + idx + 2) = h1;
        if (wantlo) {
            *(u32*)(g_sl + off + idx)     = l0;
            *(u32*)(g_sl + off + idx + 2) = l1;
        }
    }
}

// ---------------------------------------------------------------------------
// Projection GEMM, fp16 EFT: C = (Ah [+ Al]) @ Wh^T.
// Q,K (z=0,1): 2-term A.  V (z=2), O (z=3): 1-term (pure fp16 A).
// cp.async 2-stage, 512 threads (16 warps 4x4), warp tile 32x64.
// CTA tile 128x256, k-tile 32.
// smem stage: Ah(10240B) Al(10240) Bh(20480); stride 40960 B; 2 stages.
// ---------------------------------------------------------------------------
#define PJS 20

extern __shared__ u32 smdyn[];

__global__ void __launch_bounds__(512) proj_mma(float* __restrict__ fout, int qkv)
{
    const int z = qkv ? blockIdx.z : 3;
    const bool two = (z <= 1);          // 2-term A only for Q,K projections
    const int aoff = (z == 3) ? 7 * SEG : z * SEG;
    const int woff = 3 * SEG + z * WSEG;
    const __half* Agh = g_sh + aoff;
    const __half* Agl = g_sl + aoff;
    const __half* Bgh = g_sh + woff;

    const int t = threadIdx.x, lane = t & 31, wid = t >> 5;
    const int g = lane >> 2, ctg = lane & 3;
    const int wm = wid >> 2, wn = wid & 3;          // 4 x 4 warps
    const int m0 = blockIdx.y * 128, n0 = blockIdx.x * 256;

    const u32 sb = (u32)__cvta_generic_to_shared(smdyn);
    const u32 lro = ((lane & 7) + ((lane >> 3) & 1) * 8) * 80 + (lane >> 4) * 16;

    // copy mapping: A 512 uint4 (1/thread each for hi,lo); B 1024 uint4 (2/thread)
    const int ra_ = t >> 2, sa_ = t & 3;
    const u32 da_ = (u32)(ra_ * PJS + sa_ * 4) * 4;
    int rb_[2], sgb_[2]; u32 db_[2];
    #pragma unroll
    for (int u = 0; u < 2; u++) {
        const int idx = t + u * 512;
        rb_[u] = idx >> 2; sgb_[u] = idx & 3;
        db_[u] = (u32)(rb_[u] * PJS + sgb_[u] * 4) * 4;
    }

    float c[2][8][4];
    #pragma unroll
    for (int i = 0; i < 2; i++)
        #pragma unroll
        for (int j = 0; j < 8; j++)
            #pragma unroll
            for (int r = 0; r < 4; r++) c[i][j][r] = 0.f;

    auto issue = [&](int k0, int st) {
        const u32 stb = sb + (u32)st * 40960;
        cpa(stb + da_, Agh + (size_t)(m0 + ra_) * 1024 + k0 + sa_ * 8);
        if (two)
            cpa(stb + 10240 + da_, Agl + (size_t)(m0 + ra_) * 1024 + k0 + sa_ * 8);
        #pragma unroll
        for (int u = 0; u < 2; u++)
            cpa(stb + 20480 + db_[u],
                Bgh + (size_t)(n0 + rb_[u]) * 1024 + k0 + sgb_[u] * 8);
        cpc();
    };

    issue(0, 0);

    for (int kt = 0; kt < 32; kt++) {
        CPW(0);
        __syncthreads();
        if (kt < 31) issue((kt + 1) * 32, (kt + 1) & 1);

        const u32 stb = sb + (u32)(kt & 1) * 40960;
        const u32 bAh = stb, bAl = stb + 10240, bBh = stb + 20480;

        #pragma unroll
        for (int ch = 0; ch < 2; ch++) {
            u32 a[2][2][4];
            #pragma unroll
            for (int i = 0; i < 2; i++) {
                const u32 ad = (u32)(wm * 32 + i * 16) * 80 + ch * 32 + lro;
                ldsm4(a[i][0], bAh + ad);
                if (two) ldsm4(a[i][1], bAl + ad);
            }
            u32 bh_[4][4];
            #pragma unroll
            for (int jp = 0; jp < 4; jp++)
                ldsm4(bh_[jp], bBh + (u32)(wn * 64 + jp * 16) * 80 + ch * 32 + lro);
            #pragma unroll
            for (int jp = 0; jp < 4; jp++)
                #pragma unroll
                for (int jj = 0; jj < 2; jj++) {
                    const int j = jp * 2 + jj;
                    const u32 b0h = bh_[jp][jj], b1h = bh_[jp][2 + jj];
                    #pragma unroll
                    for (int i = 0; i < 2; i++) {
                        mma16816(c[i][j], a[i][0][0], a[i][0][1], a[i][0][2], a[i][0][3], b0h, b1h);
                        if (two)
                            mma16816(c[i][j], a[i][1][0], a[i][1][1], a[i][1][2], a[i][1][3], b0h, b1h);
                    }
                }
        }
    }

    // epilogue (lo halves of Q/K/V scratch are never consumed -> hi only)
    const float scale = (z == 0) ? 0.125f * 1.4426950408889634f : 1.0f;
    if (z < 3) {
        __half* Oh = g_sh + (4 + z) * SEG;
        #pragma unroll
        for (int i = 0; i < 2; i++)
            #pragma unroll
            for (int h2 = 0; h2 < 2; h2++) {
                const int m = m0 + wm * 32 + i * 16 + h2 * 8 + g;
                const int b = m >> 11, tq = m & 2047;
                #pragma unroll
                for (int j = 0; j < 8; j++) {
                    const int n = n0 + wn * 64 + j * 8 + ctg * 2;
                    const int h = n >> 6, dk = n & 63;
                    __half2 hv = __floats2half2_rn(c[i][j][h2*2] * scale,
                                                   c[i][j][h2*2+1] * scale);
                    const size_t e = (((size_t)(b * HH + h) * TT + tq) << 6) + dk;
                    *(u32*)(Oh + e) = *(u32*)&hv;
                }
            }
    } else {
        #pragma unroll
        for (int i = 0; i < 2; i++)
            #pragma unroll
            for (int h2 = 0; h2 < 2; h2++) {
                const int m = m0 + wm * 32 + i * 16 + h2 * 8 + g;
                #pragma unroll
                for (int j = 0; j < 8; j++) {
                    const int n = n0 + wn * 64 + j * 8 + ctg * 2;
                    *(float2*)(fout + (size_t)m * 1024 + n)
                        = make_float2(c[i][j][h2*2], c[i][j][h2*2+1]);
                }
            }
    }
}

// ---------------------------------------------------------------------------
// Fused attention, 512 threads (16 warps), fp16, 1-term S everywhere.
// Pass A: S = Qh x Kh, row sums of exp.  Pass B: same S recompute + weights +
// 1-term AV (W fp16 x Vh).
// smem (bytes): Qh 0 | K st0 36864  st1 55296 (hi only)
//   Vh 73728 | Wh 92160 (34816) ; total 126976 B.
// ---------------------------------------------------------------------------
__global__ void __launch_bounds__(512) attn_mma(float* __restrict__ wout)
{
    __shared__ float stats[512];

    const int t = threadIdx.x, lane = t & 31, wid = t >> 5;
    const int g = lane >> 2, ctg = lane & 3;
    const int wm = wid >> 2, wn = wid & 3;          // 4 x 4 warps
    const int bh = blockIdx.y;
    const int q0 = blockIdx.x * 128;
    const int head = bh & 15, bb = bh >> 4;

    const __half* Qgh = g_sh + 4 * SEG + (size_t)bh * TT * DK;
    const __half* Kgh = g_sh + 5 * SEG + (size_t)bh * TT * DK;
    const __half* Vgh = g_sh + 6 * SEG + (size_t)bh * TT * DK;

    const u32 sb = (u32)__cvta_generic_to_shared(smdyn);
    u32* sWh = smdyn + 23040;                       // u32 index of Wh region
    const u32 bQh = sb;
    const u32 bVh = sb + 73728;
    const u32 bWh = sb + 92160;

    const u32 lro36 = ((lane & 7) + ((lane >> 3) & 1) * 8) * 144 + (lane >> 4) * 16;
    const u32 lro68 = ((lane & 7) + ((lane >> 3) & 1) * 8) * 272 + (lane >> 4) * 16;

    // copy mapping: 128x64 fp16 tile = 1024 uint4, 2 per thread
    int cr[2], cs[2]; u32 cd[2];
    #pragma unroll
    for (int u = 0; u < 2; u++) {
        const int idx = t + u * 512;
        cr[u] = idx >> 3; cs[u] = idx & 7;
        cd[u] = (u32)(cr[u] * 36 + cs[u] * 4) * 4;
    }

    // ---- load Q tile (hi only; lo chain is dead) ----
    #pragma unroll
    for (int u = 0; u < 2; u++)
        *(uint4*)(smdyn + cr[u] * 36 + cs[u] * 4) =
            *(const uint4*)(Qgh + (size_t)(q0 + cr[u]) * DK + cs[u] * 8);

    float l_[4] = {0.f, 0.f, 0.f, 0.f};

    auto issueK = [&](int kt, int st) {
        const u32 stb = sb + 36864u + (u32)st * 18432u;
        #pragma unroll
        for (int u = 0; u < 2; u++)
            cpa(stb + cd[u], Kgh + (size_t)(kt * 128 + cr[u]) * DK + cs[u] * 8);
        cpc();
    };

    issueK(0, 0);

    // ============================ pass A ============================
    for (int kt = 0; kt < 16; kt++) {
        CPW(0);
        __syncthreads();
        if (kt < 15) issueK(kt + 1, (kt + 1) & 1);

        const u32 bKh = sb + 36864u + (u32)(kt & 1) * 18432u;

        float s[2][4][4];
        #pragma unroll
        for (int i = 0; i < 2; i++)
            #pragma unroll
            for (int j = 0; j < 4; j++)
                #pragma unroll
                for (int r = 0; r < 4; r++) s[i][j][r] = 0.f;

        #pragma unroll
        for (int ch = 0; ch < 4; ch++) {
            u32 a[2][4];
            #pragma unroll
            for (int i = 0; i < 2; i++)
                ldsm4(a[i], bQh + (u32)(wm * 32 + i * 16) * 144 + ch * 32 + lro36);
            #pragma unroll
            for (int jp = 0; jp < 2; jp++) {
                u32 bfh[4];
                ldsm4(bfh, bKh + (u32)(wn * 32 + jp * 16) * 144 + ch * 32 + lro36);
                #pragma unroll
                for (int jj = 0; jj < 2; jj++) {
                    const int j = jp * 2 + jj;
                    #pragma unroll
                    for (int i = 0; i < 2; i++)
                        mma16816(s[i][j], a[i][0], a[i][1], a[i][2], a[i][3],
                                 bfh[jj], bfh[2 + jj]);
                }
            }
        }

        #pragma unroll
        for (int i = 0; i < 2; i++)
            #pragma unroll
            for (int h2 = 0; h2 < 2; h2++) {
                float sum = 0.f;
                #pragma unroll
                for (int j = 0; j < 4; j++)
                    sum += ex2(s[i][j][h2*2]) + ex2(s[i][j][h2*2+1]);
                sum += __shfl_xor_sync(0xffffffffu, sum, 1);
                sum += __shfl_xor_sync(0xffffffffu, sum, 2);
                l_[i * 2 + h2] += sum;
            }
    }

    // ---- merge wn quarters ----
    __syncthreads();
    if (ctg == 0) {
        #pragma unroll
        for (int i = 0; i < 2; i++)
            #pragma unroll
            for (int h2 = 0; h2 < 2; h2++) {
                const int row = wm * 32 + i * 16 + h2 * 8 + g;
                stats[row * 4 + wn] = l_[i * 2 + h2];
            }
    }
    __syncthreads();
    float inv[4];
    #pragma unroll
    for (int i = 0; i < 2; i++)
        #pragma unroll
        for (int h2 = 0; h2 < 2; h2++) {
            const int row = wm * 32 + i * 16 + h2 * 8 + g;
            inv[i * 2 + h2] = 1.f / (stats[row * 4 + 0] + stats[row * 4 + 1]
                                   + stats[row * 4 + 2] + stats[row * 4 + 3]);
        }

    float o[2][2][4];
    #pragma unroll
    for (int i = 0; i < 2; i++)
        #pragma unroll
        for (int j = 0; j < 2; j++)
            #pragma unroll
            for (int r = 0; r < 4; r++) o[i][j][r] = 0.f;

    auto issueV = [&](int kt) {
        #pragma unroll
        for (int u = 0; u < 2; u++)
            cpa(bVh + cd[u], Vgh + (size_t)(kt * 128 + cr[u]) * DK + cs[u] * 8);
        cpc();
    };

    issueK(0, 0);

    // ============================ pass B ============================
    for (int kt = 0; kt < 16; kt++) {
        CPW(0);
        __syncthreads();
        issueV(kt);
        if (kt < 15) issueK(kt + 1, (kt + 1) & 1);

        const u32 bKh = sb + 36864u + (u32)(kt & 1) * 18432u;

        float s[2][4][4];
        #pragma unroll
        for (int i = 0; i < 2; i++)
            #pragma unroll
            for (int j = 0; j < 4; j++)
                #pragma unroll
                for (int r = 0; r < 4; r++) s[i][j][r] = 0.f;

        #pragma unroll
        for (int ch = 0; ch < 4; ch++) {
            u32 a[2][4];
            #pragma unroll
            for (int i = 0; i < 2; i++)
                ldsm4(a[i], bQh + (u32)(wm * 32 + i * 16) * 144 + ch * 32 + lro36);
            #pragma unroll
            for (int jp = 0; jp < 2; jp++) {
                u32 bfh[4];
                ldsm4(bfh, bKh + (u32)(wn * 32 + jp * 16) * 144 + ch * 32 + lro36);
                #pragma unroll
                for (int jj = 0; jj < 2; jj++) {
                    const int j = jp * 2 + jj;
                    #pragma unroll
                    for (int i = 0; i < 2; i++)
                        mma16816(s[i][j], a[i][0], a[i][1], a[i][2], a[i][3],
                                 bfh[jj], bfh[2 + jj]);
                }
            }
        }

        // normalized weights -> gmem + single-fp16 W into smem
        #pragma unroll
        for (int i = 0; i < 2; i++)
            #pragma unroll
            for (int h2 = 0; h2 < 2; h2++) {
                const int idx = i * 2 + h2;
                const int row = wm * 32 + i * 16 + h2 * 8 + g;
                #pragma unroll
                for (int j = 0; j < 4; j++) {
                    const float w0 = ex2(s[i][j][h2*2])   * inv[idx];
                    const float w1 = ex2(s[i][j][h2*2+1]) * inv[idx];
                    if (wout)
                        *(float2*)(wout + ((size_t)bh * TT + q0 + row) * TT
                                        + kt * 128 + wn * 32 + j * 8 + ctg * 2)
                            = make_float2(w0, w1);
                    __half2 wh2 = __floats2half2_rn(w0, w1);
                    sWh[row * 68 + wn * 16 + j * 4 + ctg] = *(u32*)&wh2;
                }
            }

        if (kt < 15) { CPW(1); } else { CPW(0); }
        __syncthreads();

        // AV: O += W @ V   (single term: W x Vh)
        #pragma unroll
        for (int ch = 0; ch < 8; ch++) {
            u32 aw[2][4];
            #pragma unroll
            for (int i = 0; i < 2; i++)
                ldsm4(aw[i], bWh + (u32)(wm * 32 + i * 16) * 272 + ch * 32 + lro68);
            u32 bvh[4];
            const u32 vd = (u32)(ch * 16) * 144 + (u32)(wn * 16) * 2 + lro36;
            ldsm4t(bvh, bVh + vd);
            #pragma unroll
            for (int j = 0; j < 2; j++) {
                #pragma unroll
                for (int i = 0; i < 2; i++)
                    mma16816(o[i][j], aw[i][0], aw[i][1], aw[i][2], aw[i][3],
                             bvh[j * 2], bvh[j * 2 + 1]);
            }
        }
    }

    // epilogue: O -> attn scratch hi only (O-projection is 1-term)
    __half* Oh = g_sh + 7 * SEG;
    #pragma unroll
    for (int i = 0; i < 2; i++)
        #pragma unroll
        for (int h2 = 0; h2 < 2; h2++) {
            const int row = q0 + wm * 32 + i * 16 + h2 * 8 + g;
            #pragma unroll
            for (int j = 0; j < 2; j++) {
                const int col = head * 64 + wn * 16 + j * 8 + ctg * 2;
                __half2 hv = __floats2half2_rn(o[i][j][h2*2], o[i][j][h2*2+1]);
                const size_t e = ((size_t)bb * TT + row) * DD + col;
                *(u32*)(Oh + e) = *(u32*)&hv;
            }
        }
}

// ---------------------------------------------------------------------------
extern "C" void kernel_launch(void* const* d_in, const int* in_sizes, int n_in,
                              void* d_out, int out_size)
{
    const float* query = (const float*)d_in[0];
    const float* key_  = (const float*)d_in[1];
    const float* value = (const float*)d_in[2];
    const float* W_q   = (const float*)d_in[3];
    const float* W_k   = (const float*)d_in[4];
    const float* W_v   = (const float*)d_in[5];
    const float* W_o   = (const float*)d_in[6];

    split_inputs<<<dim3(1024, 7), 256>>>(query, key_, value, W_q, W_k, W_v, W_o);

    const int psmem = 81920;
    cudaFuncSetAttribute(proj_mma,
                         cudaFuncAttributeMaxDynamicSharedMemorySize, psmem);
    proj_mma<<<dim3(4, 32, 3), 512, psmem>>>(nullptr, 1);   // Q, K, V

    const size_t OUT_E = (size_t)BB * TT * DD;
    const size_t W_E   = (size_t)BB * HH * TT * (size_t)TT;
    float* wout = nullptr;
    if ((size_t)out_size >= OUT_E + W_E)
        wout = (float*)d_out + OUT_E;

    const int asmem = 126976;
    cudaFuncSetAttribute(attn_mma,
                         cudaFuncAttributeMaxDynamicSharedMemorySize, asmem);
    attn_mma<<<dim3(TT / 128, BB * HH), 512, asmem>>>(wout);

    proj_mma<<<dim3(4, 32, 1), 512, psmem>>>((float*)d_out, 0);   // O projection
}